// round 6
// baseline (speedup 1.0000x reference)
#include <cuda_runtime.h>
#include <cstdint>

#define MAX_B 16384
__device__ float g_row_loss[MAX_B];
__device__ unsigned int g_done = 0;   // reset by finalizer each launch -> graph-replay safe

__device__ __forceinline__ float fast_rcp(float x) {
    float r;
    asm("rcp.approx.f32 %0, %1;" : "=f"(r) : "f"(x));
    return r;
}

__device__ __forceinline__ float stable_s(float x) {
    // s(x) = x+1 if x>=0 else 1/(1-x). approx rcp: <=1 ulp, fine for 1e-3 tol.
    return (x >= 0.0f) ? (x + 1.0f) : fast_rcp(1.0f - x);
}

__device__ __forceinline__ float warp_reduce(float v) {
    #pragma unroll
    for (int off = 16; off > 0; off >>= 1)
        v += __shfl_down_sync(0xFFFFFFFFu, v, off);
    return v;
}

template <int NTHR>
__global__ void __launch_bounds__(NTHR, 3)
stablemax_fused_kernel(const float* __restrict__ logits,
                       const int* __restrict__ targets,
                       float* __restrict__ out,
                       int B, int C) {
    const int tid = threadIdx.x;
    const int wid = tid >> 5, lid = tid & 31;
    __shared__ float warp_sums[NTHR / 32];
    __shared__ bool is_last;

    // ---- persistent row loop: no wave transitions ----
    for (int r = blockIdx.x; r < B; r += gridDim.x) {
        const float* __restrict__ row = logits + (size_t)r * (size_t)C;

        // alignment head: rows are only 4B-aligned (C*4 % 16 == 4)
        uintptr_t addr = (uintptr_t)row;
        int head = ((16 - (int)(addr & 15)) & 15) >> 2;
        if (head > C) head = C;

        float acc0 = 0.0f, acc1 = 0.0f, acc2 = 0.0f, acc3 = 0.0f;
        if (tid < head) acc0 += stable_s(__ldcs(row + tid));

        const int n_vec = (C - head) >> 2;
        const float4* __restrict__ vrow = (const float4*)(row + head);

        int i = tid;
        for (; i + 3 * NTHR < n_vec; i += 4 * NTHR) {
            float4 a = __ldcs(vrow + i);
            float4 b = __ldcs(vrow + i + NTHR);
            float4 c = __ldcs(vrow + i + 2 * NTHR);
            float4 d = __ldcs(vrow + i + 3 * NTHR);
            acc0 += stable_s(a.x) + stable_s(a.y) + stable_s(a.z) + stable_s(a.w);
            acc1 += stable_s(b.x) + stable_s(b.y) + stable_s(b.z) + stable_s(b.w);
            acc2 += stable_s(c.x) + stable_s(c.y) + stable_s(c.z) + stable_s(c.w);
            acc3 += stable_s(d.x) + stable_s(d.y) + stable_s(d.z) + stable_s(d.w);
        }
        for (; i < n_vec; i += NTHR) {
            float4 a = __ldcs(vrow + i);
            acc0 += stable_s(a.x) + stable_s(a.y) + stable_s(a.z) + stable_s(a.w);
        }

        const int tail_start = head + (n_vec << 2);
        if (tid < C - tail_start) acc0 += stable_s(__ldcs(row + tail_start + tid));

        float local = (acc0 + acc1) + (acc2 + acc3);

        float wsum = warp_reduce(local);
        if (lid == 0) warp_sums[wid] = wsum;
        __syncthreads();
        if (wid == 0) {
            float v = (lid < NTHR / 32) ? warp_sums[lid] : 0.0f;
            v = warp_reduce(v);
            if (lid == 0) {
                float denom = fmaxf(v, 1e-12f);
                int t = targets[r];
                if (t < 0) t = 0;
                if (t >= C) t = C - 1;
                float s_t = stable_s(__ldg(row + t));
                g_row_loss[r] = -logf(fmaxf(s_t / denom, 1e-12f));
            }
        }
        __syncthreads();   // protect warp_sums reuse on next row
    }

    // ---- fused finish: last CTA to arrive computes the mean (fixed order) ----
    __threadfence();       // make this CTA's g_row_loss writes visible
    if (tid == 0) {
        unsigned int ticket = atomicAdd(&g_done, 1u);
        is_last = (ticket == gridDim.x - 1);
    }
    __syncthreads();
    if (is_last) {
        __threadfence();   // acquire: see all CTAs' row losses
        float local = 0.0f;
        for (int i = tid; i < B; i += NTHR)
            local += g_row_loss[i];
        float wsum = warp_reduce(local);
        if (lid == 0) warp_sums[wid] = wsum;
        __syncthreads();
        if (wid == 0) {
            float v = (lid < NTHR / 32) ? warp_sums[lid] : 0.0f;
            v = warp_reduce(v);
            if (lid == 0) {
                out[0] = v / (float)B;
                g_done = 0;          // reset for next graph replay
            }
        }
    }
}

extern "C" void kernel_launch(void* const* d_in, const int* in_sizes, int n_in,
                              void* d_out, int out_size) {
    const float* logits = (const float*)d_in[0];
    const int* targets = (const int*)d_in[1];
    const int B = in_sizes[1];
    const int C = in_sizes[0] / B;

    const int NBLK = 148 * 3;   // persistent: one wave at occupancy 3
    stablemax_fused_kernel<512><<<NBLK, 512>>>(logits, targets, (float*)d_out, B, C);
}

// round 7
// speedup vs baseline: 1.1657x; 1.1657x over previous
#include <cuda_runtime.h>
#include <cstdint>

#define MAX_B 16384
__device__ float g_row_loss[MAX_B];
__device__ unsigned int g_done = 0;   // reset by finalizer each launch -> graph-replay safe

__device__ __forceinline__ float fast_rcp(float x) {
    float r;
    asm("rcp.approx.f32 %0, %1;" : "=f"(r) : "f"(x));
    return r;
}

__device__ __forceinline__ float stable_s(float x) {
    // t = 1+|x|  (|x| is a free operand modifier)
    // s(x) = x>=0 ? 1+x : 1/(1-x)  ==  x>=0 ? t : rcp(t)
    float t = 1.0f + fabsf(x);
    return (x >= 0.0f) ? t : fast_rcp(t);
}

__device__ __forceinline__ float warp_reduce(float v) {
    #pragma unroll
    for (int off = 16; off > 0; off >>= 1)
        v += __shfl_down_sync(0xFFFFFFFFu, v, off);
    return v;
}

template <int NTHR>
__global__ void __launch_bounds__(NTHR)
stablemax_fused_kernel(const float* __restrict__ logits,
                       const int* __restrict__ targets,
                       float* __restrict__ out,
                       int B, int C) {
    const int r = blockIdx.x;
    const float* __restrict__ row = logits + (size_t)r * (size_t)C;
    const int tid = threadIdx.x;
    const int wid = tid >> 5, lid = tid & 31;
    __shared__ float warp_sums[NTHR / 32];
    __shared__ bool is_last;

    // ---- alignment head: rows are only 4B-aligned (C*4 % 16 == 4) ----
    uintptr_t addr = (uintptr_t)row;
    int head = ((16 - (int)(addr & 15)) & 15) >> 2;
    if (head > C) head = C;

    float acc0 = 0.0f, acc1 = 0.0f, acc2 = 0.0f, acc3 = 0.0f;
    if (tid < head) acc0 += stable_s(__ldcs(row + tid));

    const int n_vec = (C - head) >> 2;
    const float4* __restrict__ vrow = (const float4*)(row + head);

    // ---- vector body: 4x unrolled, 4 independent accumulators for MLP ----
    int i = tid;
    for (; i + 3 * NTHR < n_vec; i += 4 * NTHR) {
        float4 a = __ldcs(vrow + i);
        float4 b = __ldcs(vrow + i + NTHR);
        float4 c = __ldcs(vrow + i + 2 * NTHR);
        float4 d = __ldcs(vrow + i + 3 * NTHR);
        acc0 += stable_s(a.x) + stable_s(a.y) + stable_s(a.z) + stable_s(a.w);
        acc1 += stable_s(b.x) + stable_s(b.y) + stable_s(b.z) + stable_s(b.w);
        acc2 += stable_s(c.x) + stable_s(c.y) + stable_s(c.z) + stable_s(c.w);
        acc3 += stable_s(d.x) + stable_s(d.y) + stable_s(d.z) + stable_s(d.w);
    }
    for (; i < n_vec; i += NTHR) {
        float4 a = __ldcs(vrow + i);
        acc0 += stable_s(a.x) + stable_s(a.y) + stable_s(a.z) + stable_s(a.w);
    }

    // ---- scalar tail ----
    const int tail_start = head + (n_vec << 2);
    if (tid < C - tail_start) acc0 += stable_s(__ldcs(row + tail_start + tid));

    float local = (acc0 + acc1) + (acc2 + acc3);

    // ---- block reduction + per-row loss ----
    float wsum = warp_reduce(local);
    if (lid == 0) warp_sums[wid] = wsum;
    __syncthreads();
    if (wid == 0) {
        float v = (lid < NTHR / 32) ? warp_sums[lid] : 0.0f;
        v = warp_reduce(v);
        if (lid == 0) {
            float denom = fmaxf(v, 1e-12f);
            int t = __ldg(targets + r);
            if (t < 0) t = 0;
            if (t >= C) t = C - 1;                 // defensive clamp, no-op for valid data
            float s_t = stable_s(__ldg(row + t));
            g_row_loss[r] = -logf(fmaxf(s_t / denom, 1e-12f));
        }
    }

    // ---- fused finish: last CTA to arrive computes the mean (fixed order) ----
    __threadfence();       // publish this CTA's row loss
    __syncthreads();       // all threads past the g_row_loss write point
    if (tid == 0) {
        unsigned int ticket = atomicAdd(&g_done, 1u);
        is_last = (ticket == (unsigned int)gridDim.x - 1u);
    }
    __syncthreads();
    if (is_last) {
        __threadfence();   // acquire: see all CTAs' row losses
        float local2 = 0.0f;
        for (int j = tid; j < B; j += NTHR)
            local2 += g_row_loss[j];
        float wsum2 = warp_reduce(local2);
        if (lid == 0) warp_sums[wid] = wsum2;
        __syncthreads();
        if (wid == 0) {
            float v = (lid < NTHR / 32) ? warp_sums[lid] : 0.0f;
            v = warp_reduce(v);
            if (lid == 0) {
                out[0] = v / (float)B;
                g_done = 0;          // reset for next graph replay
            }
        }
    }
}

extern "C" void kernel_launch(void* const* d_in, const int* in_sizes, int n_in,
                              void* d_out, int out_size) {
    const float* logits = (const float*)d_in[0];
    const int* targets = (const int*)d_in[1];
    const int B = in_sizes[1];
    const int C = in_sizes[0] / B;

    stablemax_fused_kernel<512><<<B, 512>>>(logits, targets, (float*)d_out, B, C);
}